// round 4
// baseline (speedup 1.0000x reference)
#include <cuda_runtime.h>
#include <cuda_bf16.h>
#include <math.h>

// Problem constants
#define B_   4
#define C_   128
#define H_   64
#define W_   64
#define OUT_ 128
#define LK   25

typedef unsigned long long u64;

// Device scratch
__device__ float g_w1r[C_ * 9 * 28];      // [c][tap][k padded to 28]
__device__ float g_w2d[C_ * OUT_ * 2];    // [c][o] duplicated pairs (w,w)

// packed fp32x2 FMA: d = a*b + d (two fp32 lanes, one instruction)
__device__ __forceinline__ void ffma2(u64& d, u64 a, u64 b) {
    asm("fma.rn.f32x2 %0, %1, %2, %0;" : "+l"(d) : "l"(a), "l"(b));
}
__device__ __forceinline__ u64 bcast2(float v) {
    u64 r; asm("mov.b64 %0, {%1, %1};" : "=l"(r) : "f"(v)); return r;
}
__device__ __forceinline__ float2 unpack2(u64 v) {
    float2 r; asm("mov.b64 {%0, %1}, %2;" : "=f"(r.x), "=f"(r.y) : "l"(v)); return r;
}

// ---------------------------------------------------------------------------
// Kernel 0: weight preprocessing (source-coalesced)
// ---------------------------------------------------------------------------
__global__ void prep_kernel(const float* __restrict__ w1,
                            const float* __restrict__ w2) {
    int i = blockIdx.x * blockDim.x + threadIdx.x;
    if (i < LK * C_ * 9) {
        int k   = i / (C_ * 9);
        int rem = i - k * (C_ * 9);      // c*9 + t
        g_w1r[rem * 28 + k] = w1[i];
    }
    int j = i - LK * C_ * 9;
    if (j >= 0 && j < C_ * 9 * 3) {
        int ct = j / 3;
        int kk = 25 + (j - ct * 3);
        g_w1r[ct * 28 + kk] = 0.f;
    }
    if (i < C_ * OUT_) {
        int o = i >> 7;
        int c = i & 127;
        float4 p = ((const float4*)w2)[i];       // w2[o][4c..4c+3]
        float v = p.x + p.y + p.z + p.w;
        g_w2d[c * 256 + 2 * o]     = v;          // duplicated pair
        g_w2d[c * 256 + 2 * o + 1] = v;
    }
}

// ---------------------------------------------------------------------------
// Fused kernel, 256 threads / block, 2 blocks/SM.
// smem: xs [128][144] 18432 | yb 8192 (wbuf->red->ys) | sk [26][64] 1664
// ---------------------------------------------------------------------------
#define SM_XS   (C_ * 144)
#define SM_YB   8192
#define SM_SK   (26 * 64)
#define SM_TOT  ((SM_XS + SM_YB + SM_SK) * 4)

__global__ void __launch_bounds__(256, 2)
fused_kernel(const float* __restrict__ x, const float* __restrict__ b1,
             const float* __restrict__ b2, float* __restrict__ out) {
    extern __shared__ float sm[];
    float* xs = sm;
    float* yb = sm + SM_XS;          // wbuf / red / ys (time-shared)
    float* sk = sm + SM_XS + SM_YB;  // softmax [k][px]

    int tid = threadIdx.x;
    int blk = blockIdx.x;
    int b   = blk >> 6;
    int t   = blk & 63;
    int h0  = (t >> 3) * 8;
    int w0  = (t & 7) * 8;
    const float* xb = x + b * C_ * H_ * W_;

    // ---- load 12x12 halo-2 tile (zero pad) ----
    for (int i = tid; i < C_ * 144; i += 256) {
        int c   = i / 144;
        int rem = i - c * 144;
        int yy  = rem / 12;
        int xx  = rem - yy * 12;
        int h = h0 - 2 + yy, w = w0 - 2 + xx;
        float v = 0.f;
        if ((unsigned)h < H_ && (unsigned)w < W_) v = xb[(c * H_ + h) * W_ + w];
        xs[i] = v;
    }

    // ---- conv1: cg = channel group, one pixel per thread, packed FFMA2 ----
    int cg  = tid >> 6;              // 0..3
    int px  = tid & 63;
    int py  = px >> 3;
    int pxx = px & 7;

    u64 acc2[12];                    // k pairs (0,1)..(22,23)
    float acc24 = 0.f;
    u64 zero2 = bcast2(0.f);
#pragma unroll
    for (int k = 0; k < 12; k++) acc2[k] = zero2;

    for (int j = 0; j < 4; j++) {
        __syncthreads();                       // xs ready (j=0) / wbuf free
        const float* src = g_w1r + j * (32 * 9 * 28);
        for (int i = tid; i < 32 * 9 * 28; i += 256) yb[i] = src[i];
        __syncthreads();

#pragma unroll 2
        for (int cc = 0; cc < 8; cc++) {
            int cl = cc * 4 + cg;              // local channel in chunk
            int c  = j * 32 + cl;              // global channel
            const float* xc = xs + c * 144;
            float xv[9];
#pragma unroll
            for (int dy = 0; dy < 3; dy++)
#pragma unroll
                for (int dx = 0; dx < 3; dx++)
                    xv[dy * 3 + dx] = xc[(py + 1 + dy) * 12 + pxx + 1 + dx];
            const float* wp = yb + cl * (9 * 28);
#pragma unroll
            for (int t9 = 0; t9 < 9; t9++) {
                const ulonglong2* w2p = (const ulonglong2*)(wp + t9 * 28);
                float a0 = xv[t9];
                u64  a2 = bcast2(a0);
#pragma unroll
                for (int kk = 0; kk < 6; kk++) {
                    ulonglong2 wv = w2p[kk];   // LDS.128 -> 2 packed pairs
                    ffma2(acc2[2 * kk],     a2, wv.x);
                    ffma2(acc2[2 * kk + 1], a2, wv.y);
                }
                acc24 += a0 * wp[t9 * 28 + 24];
            }
        }
    }

    __syncthreads();
    // stash partials: red[(cg*64+px)*27 + k]  (stride 27: conflict-free)
    {
        float* rp = yb + (cg * 64 + px) * 27;
#pragma unroll
        for (int k = 0; k < 12; k++) {
            float2 f = unpack2(acc2[k]);
            rp[2 * k]     = f.x;
            rp[2 * k + 1] = f.y;
        }
        rp[24] = acc24;
    }
    __syncthreads();

    // ---- softmax: one thread per pixel ----
    if (tid < 64) {
        int p = tid;
        float s[25];
        float m = -1e30f;
#pragma unroll
        for (int k = 0; k < 25; k++) {
            float v = yb[(0 * 64 + p) * 27 + k]
                    + yb[(1 * 64 + p) * 27 + k]
                    + yb[(2 * 64 + p) * 27 + k]
                    + yb[(3 * 64 + p) * 27 + k]
                    + b1[k];
            s[k] = v;
            m = fmaxf(m, v);
        }
        float tot = 0.f;
#pragma unroll
        for (int k = 0; k < 25; k++) { s[k] = __expf(s[k] - m); tot += s[k]; }
        float inv = 1.f / tot;
#pragma unroll
        for (int k = 0; k < 25; k++) sk[k * 64 + p] = s[k] * inv;
    }
    __syncthreads();

    // ---- y phase: y[c][px] = sum_k s[px][k] * window ----
    {
        int cq  = tid >> 6;
        float s[25];
#pragma unroll
        for (int k = 0; k < 25; k++) s[k] = sk[k * 64 + px];
        const float* xw = xs + py * 12 + pxx;
#pragma unroll 2
        for (int cc = 0; cc < 32; cc++) {
            int c = cq * 32 + cc;
            const float* xc = xw + c * 144;
            float a = 0.f;
#pragma unroll
            for (int ky = 0; ky < 5; ky++)
#pragma unroll
                for (int kx = 0; kx < 5; kx++)
                    a += s[ky * 5 + kx] * xc[ky * 12 + kx];
            yb[c * 64 + px] = a;              // ys (red fully consumed)
        }
    }
    __syncthreads();

    // ---- z phase: packed over pixel pairs; w2 pre-duplicated -> no packing ----
    {
        int w = tid >> 5;                     // warp -> 8 px (one source row)
        int l = tid & 31;                     // lane -> o = 4l..4l+3
        u64 za[4][4];                         // [px-pair][o]  (z[2p],z[2p+1])
#pragma unroll
        for (int pp = 0; pp < 4; pp++)
#pragma unroll
            for (int q = 0; q < 4; q++) za[pp][q] = zero2;

        const float* wd  = g_w2d + 8 * l;     // duplicated pairs for o=4l..4l+3
        const float* ysw = yb + w * 8;
#pragma unroll 4
        for (int c = 0; c < 128; c++) {
            ulonglong2 wa = *(const ulonglong2*)(wd + c * 256);      // (w0,w0),(w1,w1)
            ulonglong2 wb = *(const ulonglong2*)(wd + c * 256 + 4);  // (w2,w2),(w3,w3)
            ulonglong2 ya = *(const ulonglong2*)(ysw + c * 64);      // (y0,y1),(y2,y3)
            ulonglong2 yc = *(const ulonglong2*)(ysw + c * 64 + 4);  // (y4,y5),(y6,y7)
            u64 yp[4] = {ya.x, ya.y, yc.x, yc.y};
#pragma unroll
            for (int pp = 0; pp < 4; pp++) {
                ffma2(za[pp][0], yp[pp], wa.x);
                ffma2(za[pp][1], yp[pp], wa.y);
                ffma2(za[pp][2], yp[pp], wb.x);
                ffma2(za[pp][3], yp[pp], wb.y);
            }
        }

        float4 bb = *(const float4*)(b2 + 4 * l);
        float bq[4] = {bb.x, bb.y, bb.z, bb.w};
        int hh = h0 + w;                      // source row
#pragma unroll
        for (int q = 0; q < 4; q++) {
            int o = 4 * l + q;
            float* rowp = out + (((size_t)(b * OUT_ + o) * (2 * H_)) + 2 * hh) * (2 * W_) + 2 * w0;
#pragma unroll
            for (int pp = 0; pp < 4; pp++) {
                float2 f = unpack2(za[pp][q]);
                float z0 = f.x + bq[q];
                float z1 = f.y + bq[q];
                float4 v = make_float4(z0, z0, z1, z1);
                *(float4*)(rowp + 4 * pp)          = v;   // row 2h
                *(float4*)(rowp + 2 * W_ + 4 * pp) = v;   // row 2h+1
            }
        }
    }
}

// ---------------------------------------------------------------------------
extern "C" void kernel_launch(void* const* d_in, const int* in_sizes, int n_in,
                              void* d_out, int out_size) {
    const float* x  = (const float*)d_in[0];
    const float* w1 = (const float*)d_in[1];
    const float* b1 = (const float*)d_in[2];
    const float* w2 = (const float*)d_in[3];
    const float* b2 = (const float*)d_in[4];
    float* out = (float*)d_out;

    cudaFuncSetAttribute(fused_kernel,
                         cudaFuncAttributeMaxDynamicSharedMemorySize, SM_TOT);

    prep_kernel<<<(LK * C_ * 9 + C_ * 9 * 3 + 255) / 256, 256>>>(w1, w2);
    fused_kernel<<<256, 256, SM_TOT>>>(x, b1, b2, out);
}

// round 5
// speedup vs baseline: 1.5971x; 1.5971x over previous
#include <cuda_runtime.h>
#include <cuda_bf16.h>
#include <math.h>

// Problem constants
#define B_   4
#define C_   128
#define H_   64
#define W_   64
#define OUT_ 128
#define LK   25

typedef unsigned int uint;

// ---------------------------------------------------------------------------
// Device scratch
// ---------------------------------------------------------------------------
__device__ uint4 g_w1f[288 * 32];   // conv A fragments: (chunk,tap,kstep,mtile,split)
__device__ uint4 g_w2f[128 * 32];   // u-gemm A fragments: (mtile,kstep,split)
__device__ float g_u[B_ * OUT_ * H_ * W_];   // u = w2eff * x   (8 MB, L2-resident)

// pack two f32 -> bf16x2 word:  low16 = bf16(lo_src), high16 = bf16(hi_src)
__device__ __forceinline__ uint cvt2(float hi_src, float lo_src) {
    uint r;
    asm("cvt.rn.bf16x2.f32 %0, %1, %2;" : "=r"(r) : "f"(hi_src), "f"(lo_src));
    return r;
}
__device__ __forceinline__ float uaf(uint u) { return __uint_as_float(u); }

// split pair (f0 -> low lane, f1 -> high lane): returns hi-word, lo-residual-word
__device__ __forceinline__ void split2(float f0, float f1, uint& hw, uint& lw) {
    hw = cvt2(f1, f0);
    float h0 = uaf(hw << 16);
    float h1 = uaf(hw & 0xFFFF0000u);
    lw = cvt2(f1 - h1, f0 - h0);
}

// D += A(16x16) * B(16x8), bf16 in, f32 accum
__device__ __forceinline__ void mma4(float* d, uint4 A, uint b0, uint b1) {
    asm("mma.sync.aligned.m16n8k16.row.col.f32.bf16.bf16.f32 "
        "{%0,%1,%2,%3}, {%4,%5,%6,%7}, {%8,%9}, {%0,%1,%2,%3};"
        : "+f"(d[0]), "+f"(d[1]), "+f"(d[2]), "+f"(d[3])
        : "r"(A.x), "r"(A.y), "r"(A.z), "r"(A.w), "r"(b0), "r"(b1));
}

// ---------------------------------------------------------------------------
// Kernel 0: build bf16-split A fragments for both GEMMs (exact mma layout)
// frag regs r=0..3:  row = g + 8*(r&1),  col = 2*tig + 8*(r>>1)  (+col,+col+1)
// ---------------------------------------------------------------------------
__global__ void prep_kernel(const float* __restrict__ w1,
                            const float* __restrict__ w2) {
    int idx = blockIdx.x * blockDim.x + threadIdx.x;
    // ---- conv1 weight fragments: F = (((chunk*9+tap)*2+ks)*2+mt)*2+split ----
    if (idx < 36864) {
        int r = idx & 3, lane = (idx >> 2) & 31, F = idx >> 7;
        int split = F & 1, mtile = (F >> 1) & 1, kstep = (F >> 2) & 1;
        int tapch = F >> 3;
        int tap = tapch % 9, chunk = tapch / 9;
        int g = lane >> 2, tig = lane & 3;
        int row = g + 8 * (r & 1), col = 2 * tig + 8 * (r >> 1);
        int m = mtile * 16 + row;
        int c0 = chunk * 32 + kstep * 16 + col;
        int ty = tap / 3, tx = tap % 3;
        float f0 = 0.f, f1 = 0.f;
        if (m < LK) {
            f0 = w1[((m * C_ + c0) * 3 + ty) * 3 + tx];
            f1 = w1[((m * C_ + c0 + 1) * 3 + ty) * 3 + tx];
        }
        uint hw, lw; split2(f0, f1, hw, lw);
        ((uint*)g_w1f)[F * 128 + lane * 4 + r] = split ? lw : hw;
    }
    // ---- w2eff fragments: F = ((mt*8+ks)*2+split) ----
    if (idx < 16384) {
        int r = idx & 3, lane = (idx >> 2) & 31, F = idx >> 7;
        int split = F & 1, kstep = (F >> 1) & 7, mtile = F >> 4;
        int g = lane >> 2, tig = lane & 3;
        int row = g + 8 * (r & 1), col = 2 * tig + 8 * (r >> 1);
        int o = mtile * 16 + row;
        int c0 = kstep * 16 + col;
        float4 p0 = ((const float4*)w2)[o * 128 + c0];
        float4 p1 = ((const float4*)w2)[o * 128 + c0 + 1];
        float f0 = p0.x + p0.y + p0.z + p0.w;
        float f1 = p1.x + p1.y + p1.z + p1.w;
        uint hw, lw; split2(f0, f1, hw, lw);
        ((uint*)g_w2f)[F * 128 + lane * 4 + r] = split ? lw : hw;
    }
}

// ---------------------------------------------------------------------------
// Kernel 1: u = w2eff * x  (per 8x8 tile, M=128, N=64, K=128, bf16-split mma)
// smem x staging: [split][cpair 64][px 64 pad->72] words; bank = 8*tig+g  (CF)
// ---------------------------------------------------------------------------
__global__ void __launch_bounds__(256)
ugemm_kernel(const float* __restrict__ x) {
    __shared__ uint xsp[2 * 64 * 72];

    int tid = threadIdx.x;
    int blk = blockIdx.x;
    int b   = blk >> 6;
    int t   = blk & 63;
    int h0  = (t >> 3) * 8;
    int w0  = (t & 7) * 8;
    const float* xb = x + b * C_ * H_ * W_;

    // stage x tile as bf16-split channel pairs
    for (int i = tid; i < 64 * 64; i += 256) {
        int cp = i >> 6, px = i & 63;
        int py = px >> 3, pxx = px & 7;
        int c0 = cp * 2;
        float f0 = xb[(c0 * H_ + h0 + py) * W_ + w0 + pxx];
        float f1 = xb[((c0 + 1) * H_ + h0 + py) * W_ + w0 + pxx];
        uint hw, lw; split2(f0, f1, hw, lw);
        int a = cp * 72 + px;
        xsp[a] = hw;
        xsp[4608 + a] = lw;
    }
    __syncthreads();

    int w_  = tid >> 5;              // warp -> 8 px (row py = w_)
    int lane = tid & 31;
    int g = lane >> 2, tig = lane & 3;

    float dz[8][4];
#pragma unroll
    for (int mt = 0; mt < 8; mt++)
#pragma unroll
        for (int q = 0; q < 4; q++) dz[mt][q] = 0.f;

#pragma unroll 2
    for (int ks = 0; ks < 8; ks++) {
        int base = (ks * 8 + tig) * 72 + w_ * 8 + g;
        uint b0h = xsp[base],        b1h = xsp[base + 288];
        uint b0l = xsp[4608 + base], b1l = xsp[4608 + base + 288];
#pragma unroll
        for (int mt = 0; mt < 8; mt++) {
            int F = (mt * 8 + ks) * 2;
            uint4 Ah = g_w2f[F * 32 + lane];
            uint4 Al = g_w2f[(F + 1) * 32 + lane];
            mma4(dz[mt], Ah, b0h, b1h);
            mma4(dz[mt], Ah, b0l, b1l);
            mma4(dz[mt], Al, b0h, b1h);
        }
    }

    // store u: thread holds cols (2tig, 2tig+1), rows o = mt*16+g and +8
#pragma unroll
    for (int mt = 0; mt < 8; mt++) {
        int o0 = mt * 16 + g;
        size_t base0 = ((size_t)(b * OUT_ + o0) * H_ + h0 + w_) * W_ + w0 + 2 * tig;
        *(float2*)(g_u + base0) = make_float2(dz[mt][0], dz[mt][1]);
        size_t base1 = base0 + (size_t)8 * H_ * W_;
        *(float2*)(g_u + base1) = make_float2(dz[mt][2], dz[mt][3]);
    }
}

// ---------------------------------------------------------------------------
// Kernel 2: conv1 (9 shifted mma GEMMs) + softmax + 25-tap combine over u +
//           x2 upsample store.
// smem: us [128][12][12] f32 (73728B) | xsp chunk [2][16cp][104] (13312B,
//       overlaid by red [64][33]) | sk [25][66] (6600B)   => 93640 B, 2 blk/SM
// ---------------------------------------------------------------------------
#define K2_US_F   (C_ * 144)          // 18432 floats
#define K2_XSP_W  (2 * 16 * 104)      // 3328 words
#define K2_SK_F   (25 * 66)           // 1650 floats
#define K2_SMEM   ((K2_US_F + K2_XSP_W + K2_SK_F) * 4)

__global__ void __launch_bounds__(256, 2)
fused_kernel(const float* __restrict__ x, const float* __restrict__ b1,
             const float* __restrict__ b2, float* __restrict__ out) {
    extern __shared__ float sm[];
    float* us  = sm;                          // u tile fp32, halo 2
    uint*  xsp = (uint*)(sm + K2_US_F);       // conv B staging (per chunk)
    float* red = (float*)xsp;                 // overlay after conv
    float* sk  = sm + K2_US_F + K2_XSP_W;     // softmax [k][66]

    int tid = threadIdx.x;
    int blk = blockIdx.x;
    int b   = blk >> 6;
    int t   = blk & 63;
    int h0  = (t >> 3) * 8;
    int w0  = (t & 7) * 8;
    const float* xb = x + b * C_ * H_ * W_;

    // ---- load u tile (halo 2, zero pad) ----
    for (int i = tid; i < C_ * 144; i += 256) {
        int c   = i / 144;
        int rem = i - c * 144;
        int yy  = rem / 12;
        int xx  = rem - yy * 12;
        int h = h0 - 2 + yy, w = w0 - 2 + xx;
        float v = 0.f;
        if ((unsigned)h < H_ && (unsigned)w < W_)
            v = g_u[((size_t)(b * OUT_ + c) * H_ + h) * W_ + w];
        us[i] = v;
    }

    int w_  = tid >> 5;                 // warp -> pixel row py = w_
    int lane = tid & 31;
    int g = lane >> 2, tig = lane & 3;

    // ---- conv1: 4 channel chunks x 9 taps x 2 ksteps, bf16-split mma ----
    float dc[2][4];
#pragma unroll
    for (int mt = 0; mt < 2; mt++)
#pragma unroll
        for (int q = 0; q < 4; q++) dc[mt][q] = 0.f;

    for (int chunk = 0; chunk < 4; chunk++) {
        __syncthreads();                          // us done (c0) / xsp free
        // stage chunk: [split][cp 16][10x10 halo-1], pair-interleaved
        for (int i = tid; i < 1600; i += 256) {
            int cp = i / 100;
            int sp = i - cp * 100;
            int sy = sp / 10, sx = sp - sy * 10;
            int c0 = chunk * 32 + cp * 2;
            int h = h0 - 1 + sy, w = w0 - 1 + sx;
            float f0 = 0.f, f1 = 0.f;
            if ((unsigned)h < H_ && (unsigned)w < W_) {
                f0 = xb[(c0 * H_ + h) * W_ + w];
                f1 = xb[((c0 + 1) * H_ + h) * W_ + w];
            }
            uint hw, lw; split2(f0, f1, hw, lw);
            int a = cp * 104 + sy * 10 + sx;
            xsp[a] = hw;
            xsp[1664 + a] = lw;
        }
        __syncthreads();

#pragma unroll
        for (int ks = 0; ks < 2; ks++) {
#pragma unroll
            for (int tap = 0; tap < 9; tap++) {
                int ty = tap / 3, tx = tap % 3;
                int base = (ks * 8 + tig) * 104 + (w_ + ty) * 10 + (g + tx);
                uint b0h = xsp[base],        b1h = xsp[base + 416];
                uint b0l = xsp[1664 + base], b1l = xsp[1664 + base + 416];
#pragma unroll
                for (int mt = 0; mt < 2; mt++) {
                    int F = (((chunk * 9 + tap) * 2 + ks) * 2 + mt) * 2;
                    uint4 Ah = g_w1f[F * 32 + lane];
                    uint4 Al = g_w1f[(F + 1) * 32 + lane];
                    mma4(dc[mt], Ah, b0h, b1h);
                    mma4(dc[mt], Ah, b0l, b1l);
                    mma4(dc[mt], Al, b0h, b1h);
                }
            }
        }
    }

    __syncthreads();                    // xsp dead -> red overlay
    // scatter conv D to red[px][m] (stride 33)
    {
        int pxb = w_ * 8 + 2 * tig;
#pragma unroll
        for (int mt = 0; mt < 2; mt++) {
            int m0 = mt * 16 + g;
            red[pxb * 33 + m0]           = dc[mt][0];
            red[(pxb + 1) * 33 + m0]     = dc[mt][1];
            red[pxb * 33 + m0 + 8]       = dc[mt][2];
            red[(pxb + 1) * 33 + m0 + 8] = dc[mt][3];
        }
    }
    __syncthreads();

    // ---- softmax: one thread per pixel ----
    if (tid < 64) {
        int p = tid;
        float s[25];
        float m = -1e30f;
#pragma unroll
        for (int k = 0; k < 25; k++) {
            float v = red[p * 33 + k] + b1[k];
            s[k] = v;
            m = fmaxf(m, v);
        }
        float tot = 0.f;
#pragma unroll
        for (int k = 0; k < 25; k++) { s[k] = __expf(s[k] - m); tot += s[k]; }
        float inv = 1.f / tot;
#pragma unroll
        for (int k = 0; k < 25; k++) sk[k * 66 + p] = s[k] * inv;
    }
    __syncthreads();

    // ---- combine: out[o][px] = sum_k s[k][px] * u[o][px+win(k)] + b2[o] ----
    {
        int og = tid >> 5;              // o-group: 16 outputs
        int pp = tid & 31;              // pixel pair (2pp, 2pp+1)
        int py = pp >> 2;
        int pxx = (pp & 3) * 2;
        float2 s2[25];
#pragma unroll
        for (int k = 0; k < 25; k++)
            s2[k] = *(const float2*)(sk + k * 66 + 2 * pp);

        const float* ubase = us + py * 12 + pxx;
#pragma unroll 2
        for (int oi = 0; oi < 16; oi++) {
            int o = og * 16 + oi;
            const float* uc = ubase + o * 144;
            float a0 = 0.f, a1 = 0.f;
#pragma unroll
            for (int ky = 0; ky < 5; ky++) {
                const float* ur = uc + ky * 12;
                float2 v0 = *(const float2*)(ur);
                float2 v1 = *(const float2*)(ur + 2);
                float2 v2 = *(const float2*)(ur + 4);
                float v[6] = {v0.x, v0.y, v1.x, v1.y, v2.x, v2.y};
#pragma unroll
                for (int kx = 0; kx < 5; kx++) {
                    a0 += s2[ky * 5 + kx].x * v[kx];
                    a1 += s2[ky * 5 + kx].y * v[kx + 1];
                }
            }
            float bo = b2[o];
            float z0 = a0 + bo, z1 = a1 + bo;
            float4 vv = make_float4(z0, z0, z1, z1);
            size_t rowb = ((size_t)(b * OUT_ + o) * (2 * H_) + 2 * (h0 + py)) * (2 * W_)
                        + 2 * (w0 + pxx);
            *(float4*)(out + rowb)            = vv;
            *(float4*)(out + rowb + 2 * W_)   = vv;
        }
    }
}

// ---------------------------------------------------------------------------
extern "C" void kernel_launch(void* const* d_in, const int* in_sizes, int n_in,
                              void* d_out, int out_size) {
    const float* x  = (const float*)d_in[0];
    const float* w1 = (const float*)d_in[1];
    const float* b1 = (const float*)d_in[2];
    const float* w2 = (const float*)d_in[3];
    const float* b2 = (const float*)d_in[4];
    float* out = (float*)d_out;

    cudaFuncSetAttribute(fused_kernel,
                         cudaFuncAttributeMaxDynamicSharedMemorySize, K2_SMEM);

    prep_kernel<<<144, 256>>>(w1, w2);
    ugemm_kernel<<<256, 256>>>(x);
    fused_kernel<<<256, 256, K2_SMEM>>>(x, b1, b2, out);
}